// round 8
// baseline (speedup 1.0000x reference)
#include <cuda_runtime.h>

#define B_ 64
#define G_ 512
#define H_ 512
#define P_ 64
#define S_ 256
#define NPROD B_
#define NFILL (B_ * P_)
#define GRID_ (NPROD + NFILL)
#define TWO_PI_F 6.283185307179586f

// Scratch + sync state (allocation-free rule: __device__ globals, zero-init).
__device__ float g_K1[B_ * P_];
__device__ float g_K2[B_ * P_];
__device__ int   g_done;      // producers done count (reset each run)
__device__ int   g_finished;  // blocks finished count (reset each run)

// Kahan compensated add (stage-2 only). _rn blocks contraction.
__device__ __forceinline__ void kahan_add(float term, float& s, float& c) {
    float y = __fsub_rn(term, c);
    float t = __fadd_rn(s, y);
    c = __fsub_rn(__fsub_rn(t, s), y);
    s = t;
}

// ---------------------------------------------------------------------------
// One fused kernel.
//  bid <  64  : producer — K1[b,:], K2[b,:] = heads of relu(Zg@Wl+bl).
//  bid >= 64  : consumer — out[bp,l,m] = sin(K1*l)*cos(K2*m+ph)+cos(K1*l)*sin(K2*m+ph)
// Consumers spin on g_done (producers are bids 0..63 -> resident in wave 1,
// depend on nothing -> forward progress guaranteed). Flag pattern:
// release = stores, bar, fence, atomicAdd; acquire = volatile poll, fence, bar.
// Last finished block resets counters for the next graph replay.
// ---------------------------------------------------------------------------
__global__ void __launch_bounds__(256, 8) fused_kernel(
    const float* __restrict__ Zg,  const float* __restrict__ phi,
    const float* __restrict__ Wl,  const float* __restrict__ bl,
    const float* __restrict__ W1,  const float* __restrict__ b1,
    const float* __restrict__ W2,  const float* __restrict__ b2,
    float* __restrict__ out)
{
    __shared__ __align__(16) char smraw[9216];
    const int t   = threadIdx.x;   // 0..255
    const int bid = blockIdx.x;

    if (bid < NPROD) {
        // ================= producer: MLP for b = bid =================
        float*  zg  = (float*)smraw;             // [512]
        float4* ps  = (float4*)(smraw + 2048);   // [256] stage-1 partials
        float*  x   = (float*)(smraw + 6144);    // [512]
        float*  red = (float*)(smraw + 8192);    // [256] stage-2 partials
        const int b = bid;

        zg[t]       = Zg[b * G_ + t];
        zg[t + 256] = Zg[b * G_ + t + 256];
        __syncthreads();

        // Stage 1: x = relu(zg @ Wl + bl). col4 = t&127 (cols 4c..4c+3),
        // gc = t>>7 (two 256-long g-chunks). LDG.128 weights, plain FFMA.
        {
            const int col4 = t & 127;
            const int gc   = t >> 7;
            const float4* __restrict__ W4 = (const float4*)Wl;
            float4 a = make_float4(0.f, 0.f, 0.f, 0.f);
            const int g0 = gc * 256;
#pragma unroll 8
            for (int g = g0; g < g0 + 256; ++g) {
                const float  z = zg[g];
                const float4 w = W4[g * (H_ / 4) + col4];
                a.x = fmaf(z, w.x, a.x);
                a.y = fmaf(z, w.y, a.y);
                a.z = fmaf(z, w.z, a.z);
                a.w = fmaf(z, w.w, a.w);
            }
            ps[gc * 128 + col4] = a;
        }
        __syncthreads();

        if (t < 128) {
            float4 a0 = ps[t], a1 = ps[128 + t];
            const float4 bb = ((const float4*)bl)[t];
            float4 r;
            r.x = a0.x + a1.x + bb.x;
            r.y = a0.y + a1.y + bb.y;
            r.z = a0.z + a1.z + bb.z;
            r.w = a0.w + a1.w + bb.w;
            r.x = r.x > 0.f ? r.x : 0.f;
            r.y = r.y > 0.f ? r.y : 0.f;
            r.z = r.z > 0.f ? r.z : 0.f;
            r.w = r.w > 0.f ? r.w : 0.f;
            ((float4*)x)[t] = r;
        }
        __syncthreads();

        // Stage 2: K heads. p=t&63, half=(t>>6)&1, hc=t>>7 (256-long chunks),
        // Kahan partials, smem reduce.
        {
            const int p    = t & 63;
            const int half = (t >> 6) & 1;
            const int hc   = t >> 7;
            const float* __restrict__ W = half ? W2 : W1;
            float s = 0.f, c = 0.f;
            const int h0 = hc * 256;
#pragma unroll 4
            for (int h = h0; h < h0 + 256; ++h)
                kahan_add(__fmul_rn(x[h], W[h * P_ + p]), s, c);
            red[hc * 128 + (t & 127)] = __fsub_rn(s, c);
        }
        __syncthreads();

        if (t < 128) {
            const int p = t & 63;
            float k = red[t] + red[128 + t];
            if (t < 64) g_K1[b * P_ + p] = k + b1[p];
            else        g_K2[b * P_ + p] = k + b2[p];
        }
        __syncthreads();
        if (t == 0) {                 // release
            __threadfence();
            atomicAdd(&g_done, 1);
        }
    } else {
        // ================= consumer: fill tile bp =================
        const int bp = bid - NPROD;
        float* sA = (float*)smraw;
        float* cA = sA + S_;
        float* sB = cA + S_;
        float* cB = sB + S_;

        if (t == 0) {                 // acquire
            while (*(volatile int*)&g_done < NPROD) __nanosleep(64);
            __threadfence();
        }
        __syncthreads();

        const float K1 = g_K1[bp];
        const float K2 = g_K2[bp];
        const float ph = phi[bp] * TWO_PI_F;
        {
            float s, c;
            sincosf(K1 * (float)t, &s, &c);
            sA[t] = s; cA[t] = c;
            sincosf(K2 * (float)t + ph, &s, &c);
            sB[t] = s; cB[t] = c;
        }
        __syncthreads();

        const int    mi = t & 63;
        const int    r0 = t >> 6;
        const float4 sb = ((const float4*)sB)[mi];
        const float4 cb = ((const float4*)cB)[mi];
        float4* __restrict__ out4 =
            (float4*)(out + (size_t)bp * (S_ * S_));

#pragma unroll 8
        for (int i = 0; i < S_ / 4; ++i) {
            const int l  = (i << 2) + r0;
            const float sa = sA[l];
            const float ca = cA[l];
            float4 r;
            r.x = sa * cb.x + ca * sb.x;
            r.y = sa * cb.y + ca * sb.y;
            r.z = sa * cb.z + ca * sb.z;
            r.w = sa * cb.w + ca * sb.w;
            __stcs(&out4[l * (S_ / 4) + mi], r);
        }
    }

    // Replay-safe reset: last of all GRID_ blocks zeroes the counters.
    __syncthreads();
    if (t == 0) {
        __threadfence();
        int f = atomicAdd(&g_finished, 1);
        if (f == GRID_ - 1) {
            g_done = 0;
            __threadfence();
            g_finished = 0;
        }
    }
}

extern "C" void kernel_launch(void* const* d_in, const int* in_sizes, int n_in,
                              void* d_out, int out_size) {
    const float* Zg  = (const float*)d_in[0];
    const float* phi = (const float*)d_in[1];
    const float* Wl  = (const float*)d_in[2];
    const float* bl  = (const float*)d_in[3];
    const float* W1  = (const float*)d_in[4];
    const float* b1  = (const float*)d_in[5];
    const float* W2  = (const float*)d_in[6];
    const float* b2  = (const float*)d_in[7];
    float* out = (float*)d_out;

    fused_kernel<<<GRID_, 256>>>(Zg, phi, Wl, bl, W1, b1, W2, b2, out);
}

// round 9
// speedup vs baseline: 1.1768x; 1.1768x over previous
#include <cuda_runtime.h>

#define B_ 64
#define G_ 512
#define H_ 512
#define P_ 64
#define S_ 256
#define TWO_PI_F 6.283185307179586f

// Split-K partial results: [half][b*64+p]. Deterministic (no atomics);
// fill sums the two halves. Allocation-free rule: __device__ globals.
__device__ float g_K1p[2][B_ * P_];
__device__ float g_K2p[2][B_ * P_];

// ---------------------------------------------------------------------------
// Kernel 1: 128 blocks = (b, half). Block (b,hf) computes
//   x_half = relu-part: x[hf*256 .. hf*256+255] for batch b, then the
//   PARTIAL head sums  Kp[head][b,p] = sum_{h in half} x[h] * W{head}[h,p].
// 256 threads. Halved per-block weight traffic + 128-SM spread kills the
// latency exposure that made the 64-block version ~25us.
// ---------------------------------------------------------------------------
__global__ void __launch_bounds__(256) mlp_kernel(
    const float* __restrict__ Zg,  const float* __restrict__ Wl,
    const float* __restrict__ bl,  const float* __restrict__ W1,
    const float* __restrict__ b1,  const float* __restrict__ W2,
    const float* __restrict__ b2)
{
    const int b  = blockIdx.x >> 1;
    const int hf = blockIdx.x & 1;       // which 256-col half of H
    const int t  = threadIdx.x;          // 0..255

    __shared__ float  zg[G_];
    __shared__ float4 ps[4][64];         // stage-1 partials [g-chunk][col4]
    __shared__ float  xh[256];           // this half's hidden activations
    __shared__ float  red[2][128];       // stage-2 partials [h-chunk][head*64+p]

    zg[t]       = Zg[b * G_ + t];
    zg[t + 256] = Zg[b * G_ + t + 256];
    __syncthreads();

    // ---- Stage 1: xh = relu(zg @ Wl[:, hf*256 : hf*256+256] + bl_half) ----
    {
        const int c4 = t & 63;           // float4 col group within the half
        const int gc = t >> 6;           // g-chunk 0..3 (128 g each)
        const float4* __restrict__ W4 = (const float4*)Wl;
        const int colbase = hf * 64;     // float4 offset of this half
        float4 a = make_float4(0.f, 0.f, 0.f, 0.f);
        const int g0 = gc * 128;
#pragma unroll 8
        for (int g = g0; g < g0 + 128; ++g) {
            const float  z = zg[g];
            const float4 w = W4[g * (H_ / 4) + colbase + c4];  // LDG.128
            a.x = fmaf(z, w.x, a.x);
            a.y = fmaf(z, w.y, a.y);
            a.z = fmaf(z, w.z, a.z);
            a.w = fmaf(z, w.w, a.w);
        }
        ps[gc][c4] = a;
    }
    __syncthreads();

    if (t < 64) {
        float4 a0 = ps[0][t], a1 = ps[1][t], a2 = ps[2][t], a3 = ps[3][t];
        const float4 bb = ((const float4*)bl)[hf * 64 + t];
        float4 r;
        r.x = (a0.x + a1.x) + (a2.x + a3.x) + bb.x;
        r.y = (a0.y + a1.y) + (a2.y + a3.y) + bb.y;
        r.z = (a0.z + a1.z) + (a2.z + a3.z) + bb.z;
        r.w = (a0.w + a1.w) + (a2.w + a3.w) + bb.w;
        r.x = r.x > 0.f ? r.x : 0.f;
        r.y = r.y > 0.f ? r.y : 0.f;
        r.z = r.z > 0.f ? r.z : 0.f;
        r.w = r.w > 0.f ? r.w : 0.f;
        ((float4*)xh)[t] = r;
    }
    __syncthreads();

    // ---- Stage 2: partial K heads over this 256-h half ----
    {
        const int p    = t & 63;
        const int head = (t >> 6) & 1;   // 0 -> K1, 1 -> K2
        const int hc   = t >> 7;         // h-chunk 0..1 (128 each)
        const float* __restrict__ W = head ? W2 : W1;
        const int h0g = hf * 256 + hc * 128;   // global h base
        const int h0l = hc * 128;              // local (xh) base
        float a0 = 0.f, a1 = 0.f, a2 = 0.f, a3 = 0.f;
#pragma unroll 4
        for (int h = 0; h < 128; h += 4) {
            a0 = fmaf(xh[h0l + h + 0], W[(h0g + h + 0) * P_ + p], a0);
            a1 = fmaf(xh[h0l + h + 1], W[(h0g + h + 1) * P_ + p], a1);
            a2 = fmaf(xh[h0l + h + 2], W[(h0g + h + 2) * P_ + p], a2);
            a3 = fmaf(xh[h0l + h + 3], W[(h0g + h + 3) * P_ + p], a3);
        }
        red[hc][head * 64 + p] = (a0 + a1) + (a2 + a3);
    }
    __syncthreads();

    if (t < 128) {
        const int p    = t & 63;
        const int head = t >> 6;
        float k = red[0][t] + red[1][t];
        if (hf == 0) k += head ? b2[p] : b1[p];   // bias once (half 0)
        if (head == 0) g_K1p[hf][b * P_ + p] = k;
        else           g_K2p[hf][b * P_ + p] = k;
    }
}

// ---------------------------------------------------------------------------
// Kernel 2: out[b,p,l,m] = sin(K1*l + K2*m + phi*2pi)
//                        = sin(K1*l)*cos(K2*m+ph) + cos(K1*l)*sin(K2*m+ph)
// K1/K2 assembled from the two split-K partials (deterministic sum).
// One block per (b,p); body measured at 86% DRAM SOL — frozen.
// ---------------------------------------------------------------------------
__global__ void __launch_bounds__(S_) fill_kernel(const float* __restrict__ phi,
                                                  float* __restrict__ out) {
    const int bp = blockIdx.x;       // b*P + p
    const int t  = threadIdx.x;      // 0..255

    __shared__ float sA[S_], cA[S_], sB[S_], cB[S_];

    const float K1 = g_K1p[0][bp] + g_K1p[1][bp];
    const float K2 = g_K2p[0][bp] + g_K2p[1][bp];
    const float ph = phi[bp] * TWO_PI_F;

    {
        float s, c;
        sincosf(K1 * (float)t, &s, &c);
        sA[t] = s; cA[t] = c;
        sincosf(K2 * (float)t + ph, &s, &c);
        sB[t] = s; cB[t] = c;
    }
    __syncthreads();

    const int    mi = t & 63;   // float4 index within a row (m dimension)
    const int    r0 = t >> 6;   // row residue 0..3
    const float4 sb = ((const float4*)sB)[mi];
    const float4 cb = ((const float4*)cB)[mi];

    float4* __restrict__ out4 =
        (float4*)(out + (size_t)bp * (S_ * S_));

#pragma unroll 8
    for (int i = 0; i < S_ / 4; ++i) {
        const int l  = (i << 2) + r0;
        const float sa = sA[l];
        const float ca = cA[l];
        float4 r;
        r.x = sa * cb.x + ca * sb.x;
        r.y = sa * cb.y + ca * sb.y;
        r.z = sa * cb.z + ca * sb.z;
        r.w = sa * cb.w + ca * sb.w;
        __stcs(&out4[l * (S_ / 4) + mi], r);  // streaming store
    }
}

extern "C" void kernel_launch(void* const* d_in, const int* in_sizes, int n_in,
                              void* d_out, int out_size) {
    const float* Zg  = (const float*)d_in[0];
    const float* phi = (const float*)d_in[1];
    const float* Wl  = (const float*)d_in[2];
    const float* bl  = (const float*)d_in[3];
    const float* W1  = (const float*)d_in[4];
    const float* b1  = (const float*)d_in[5];
    const float* W2  = (const float*)d_in[6];
    const float* b2  = (const float*)d_in[7];
    float* out = (float*)d_out;

    mlp_kernel<<<2 * B_, 256>>>(Zg, Wl, bl, W1, b1, W2, b2);
    fill_kernel<<<B_ * P_, S_>>>(phi, out);
}

// round 13
// speedup vs baseline: 1.2743x; 1.0828x over previous
#include <cuda_runtime.h>
#include <cuda_pipeline.h>

#define B_ 64
#define G_ 512
#define H_ 512
#define P_ 64
#define S_ 256
#define HQ_ 4          // H split into 4 quarters of 128
#define BPAIRS (B_ / 2)
#define TWO_PI_F 6.283185307179586f

// Split-K partials: [h-quarter][b*64+p]. Deterministic; fill sums 4.
__device__ float g_K1p[HQ_][B_ * P_];
__device__ float g_K2p[HQ_][B_ * P_];

// ---------------------------------------------------------------------------
// Kernel 1: grid (32 b-pairs x 4 h-quarters), 256 threads.
// Block (bp, hq): x[2b x 128 cols] = relu(Zg@Wl+bl) for its quarter, then
// partial heads over those 128 h for both b's. Head weights (64KB, gmem-
// contiguous rows) prefetched via cp.async BEFORE stage 1 -> stage-2 weight
// latency fully hidden. Each Wl float4 feeds 2 b's -> traffic halved.
// ---------------------------------------------------------------------------
__global__ void __launch_bounds__(256) mlp_kernel(
    const float* __restrict__ Zg,  const float* __restrict__ Wl,
    const float* __restrict__ bl,  const float* __restrict__ W1,
    const float* __restrict__ b1,  const float* __restrict__ W2,
    const float* __restrict__ b2)
{
    extern __shared__ __align__(16) float wsm[];   // [2][128][64] = 64KB
    float* w1s = wsm;                  // [128][64]
    float* w2s = wsm + 128 * 64;       // [128][64]

    __shared__ float  zg[2][G_];       // 4KB
    __shared__ float4 ps[2][8][32];    // 8KB stage-1 partials
    __shared__ float  xh[2][128];      // 1KB
    __shared__ float  red[2][2][2][64];// 2KB [bsel][head][hc2][p]

    const int t  = threadIdx.x;        // 0..255
    const int bp = blockIdx.x >> 2;    // b-pair 0..31
    const int hq = blockIdx.x & 3;     // h-quarter 0..3
    const int b0 = bp * 2;

    // --- prefetch this quarter's head weights (rows contiguous in gmem) ---
    {
        const float4* s1 = (const float4*)(W1 + hq * 128 * P_);
        const float4* s2 = (const float4*)(W2 + hq * 128 * P_);
        float4* d1 = (float4*)w1s;
        float4* d2 = (float4*)w2s;
#pragma unroll
        for (int i = 0; i < 8; ++i) {
            __pipeline_memcpy_async(d1 + t + i * 256, s1 + t + i * 256, 16);
            __pipeline_memcpy_async(d2 + t + i * 256, s2 + t + i * 256, 16);
        }
        __pipeline_commit();
    }

    // --- load both b's inputs ---
    {
        const int bsel = t >> 7, idx = t & 127;
        ((float4*)zg[bsel])[idx] =
            ((const float4*)(Zg + (b0 + bsel) * G_))[idx];
    }
    __syncthreads();

    // ---- Stage 1: x = relu(zg @ Wl_quarter + bl_quarter), both b's ----
    {
        const int c4 = t & 31;        // float4 col within quarter (128 cols)
        const int gc = t >> 5;        // g-chunk 0..7 (64 g each)
        const float4* __restrict__ W4 = (const float4*)Wl;
        const int cbase = hq * 32;
        float4 a0 = make_float4(0.f, 0.f, 0.f, 0.f);
        float4 a1 = make_float4(0.f, 0.f, 0.f, 0.f);
        const int g0 = gc * 64;
#pragma unroll 8
        for (int g = g0; g < g0 + 64; ++g) {
            const float4 w  = W4[g * (H_ / 4) + cbase + c4];  // LDG.128
            const float  z0 = zg[0][g];
            const float  z1 = zg[1][g];
            a0.x = fmaf(z0, w.x, a0.x);  a1.x = fmaf(z1, w.x, a1.x);
            a0.y = fmaf(z0, w.y, a0.y);  a1.y = fmaf(z1, w.y, a1.y);
            a0.z = fmaf(z0, w.z, a0.z);  a1.z = fmaf(z1, w.z, a1.z);
            a0.w = fmaf(z0, w.w, a0.w);  a1.w = fmaf(z1, w.w, a1.w);
        }
        ps[0][gc][c4] = a0;
        ps[1][gc][c4] = a1;
    }
    __syncthreads();

    if (t < 64) {                     // reduce 8 g-chunks, bias, relu
        const int c4 = t & 31, bsel = t >> 5;
        float4 a = make_float4(0.f, 0.f, 0.f, 0.f);
#pragma unroll
        for (int gc = 0; gc < 8; ++gc) {
            const float4 v = ps[bsel][gc][c4];
            a.x += v.x; a.y += v.y; a.z += v.z; a.w += v.w;
        }
        const float4 bb = ((const float4*)bl)[hq * 32 + c4];
        a.x += bb.x; a.y += bb.y; a.z += bb.z; a.w += bb.w;
        a.x = a.x > 0.f ? a.x : 0.f;
        a.y = a.y > 0.f ? a.y : 0.f;
        a.z = a.z > 0.f ? a.z : 0.f;
        a.w = a.w > 0.f ? a.w : 0.f;
        ((float4*)xh[bsel])[c4] = a;
    }
    __pipeline_wait_prior(0);
    __syncthreads();

    // ---- Stage 2: partial heads from smem (both b's) ----
    {
        const int p    = t & 63;
        const int head = (t >> 6) & 1;
        const int hc2  = t >> 7;              // 0..1 (64-h subchunks)
        const float* __restrict__ ws = head ? w2s : w1s;
        const int h0 = hc2 * 64;
        float k0 = 0.f, k1 = 0.f;
#pragma unroll 8
        for (int h = h0; h < h0 + 64; ++h) {
            const float w = ws[h * 64 + p];   // stride-1 across lanes
            k0 = fmaf(xh[0][h], w, k0);
            k1 = fmaf(xh[1][h], w, k1);
        }
        red[0][head][hc2][p] = k0;
        red[1][head][hc2][p] = k1;
    }
    __syncthreads();

    {   // 256 threads = (bsel, head, p) exactly
        const int p    = t & 63;
        const int head = (t >> 6) & 1;
        const int bsel = t >> 7;
        float k = red[bsel][head][0][p] + red[bsel][head][1][p];
        if (hq == 0) k += head ? b2[p] : b1[p];   // bias once
        const int idx = (b0 + bsel) * P_ + p;
        if (head == 0) g_K1p[hq][idx] = k;
        else           g_K2p[hq][idx] = k;
    }
}

// ---------------------------------------------------------------------------
// Kernel 2: out[b,p,l,m] = sin(K1*l)*cos(K2*m+ph) + cos(K1*l)*sin(K2*m+ph).
// K assembled from 4 deterministic partials. Body at 86% DRAM SOL — frozen.
// ---------------------------------------------------------------------------
__global__ void __launch_bounds__(S_) fill_kernel(const float* __restrict__ phi,
                                                  float* __restrict__ out) {
    const int bp = blockIdx.x;       // b*P + p
    const int t  = threadIdx.x;      // 0..255

    __shared__ float sA[S_], cA[S_], sB[S_], cB[S_];

    const float K1 = (g_K1p[0][bp] + g_K1p[1][bp]) +
                     (g_K1p[2][bp] + g_K1p[3][bp]);
    const float K2 = (g_K2p[0][bp] + g_K2p[1][bp]) +
                     (g_K2p[2][bp] + g_K2p[3][bp]);
    const float ph = phi[bp] * TWO_PI_F;

    {
        float s, c;
        sincosf(K1 * (float)t, &s, &c);
        sA[t] = s; cA[t] = c;
        sincosf(K2 * (float)t + ph, &s, &c);
        sB[t] = s; cB[t] = c;
    }
    __syncthreads();

    const int    mi = t & 63;
    const int    r0 = t >> 6;
    const float4 sb = ((const float4*)sB)[mi];
    const float4 cb = ((const float4*)cB)[mi];

    float4* __restrict__ out4 = (float4*)(out + (size_t)bp * (S_ * S_));

#pragma unroll 8
    for (int i = 0; i < S_ / 4; ++i) {
        const int l  = (i << 2) + r0;
        const float sa = sA[l];
        const float ca = cA[l];
        float4 r;
        r.x = sa * cb.x + ca * sb.x;
        r.y = sa * cb.y + ca * sb.y;
        r.z = sa * cb.z + ca * sb.z;
        r.w = sa * cb.w + ca * sb.w;
        __stcs(&out4[l * (S_ / 4) + mi], r);  // streaming store
    }
}

extern "C" void kernel_launch(void* const* d_in, const int* in_sizes, int n_in,
                              void* d_out, int out_size) {
    const float* Zg  = (const float*)d_in[0];
    const float* phi = (const float*)d_in[1];
    const float* Wl  = (const float*)d_in[2];
    const float* bl  = (const float*)d_in[3];
    const float* W1  = (const float*)d_in[4];
    const float* b1  = (const float*)d_in[5];
    const float* W2  = (const float*)d_in[6];
    const float* b2  = (const float*)d_in[7];
    float* out = (float*)d_out;

    cudaFuncSetAttribute(mlp_kernel,
                         cudaFuncAttributeMaxDynamicSharedMemorySize, 65536);
    mlp_kernel<<<BPAIRS * HQ_, 256, 65536>>>(Zg, Wl, bl, W1, b1, W2, b2);
    fill_kernel<<<B_ * P_, S_>>>(phi, out);
}